// round 13
// baseline (speedup 1.0000x reference)
#include <cuda_runtime.h>
#include <cstdint>

#define BN_EPS 1e-5f

static constexpr size_t SZ64 = (size_t)16 * 256 * 64 * 64;
static constexpr size_t SZ32 = (size_t)16 * 256 * 32 * 32;

__device__ float g_A64[SZ64];
__device__ float g_B32a[SZ32];
__device__ float g_B32b[SZ32];
__device__ float g_B32c[SZ32];
__device__ float g_mean[256];
__device__ float g_r[256];
__device__ float g_cnorm[512];
__device__ int   g_q[16384];

// ---------------- packed fp32x2 helpers (each lane = exact IEEE fp32 op) ----------------
typedef unsigned long long f2;
__device__ __forceinline__ f2 pk2(float lo, float hi) {
    f2 r; asm("mov.b64 %0,{%1,%2};" : "=l"(r) : "f"(lo), "f"(hi)); return r;
}
__device__ __forceinline__ void upk2(f2 a, float& lo, float& hi) {
    asm("mov.b64 {%0,%1},%2;" : "=f"(lo), "=f"(hi) : "l"(a));
}
__device__ __forceinline__ f2 fma2(f2 a, f2 b, f2 c) {
    f2 d; asm("fma.rn.f32x2 %0,%1,%2,%3;" : "=l"(d) : "l"(a), "l"(b), "l"(c)); return d;
}
__device__ __forceinline__ f2 lds2(const float* p) { return *(const f2*)p; }  // 8B-aligned

// ---- BN batch stats: mean + r = 1/sqrt(var+eps), jnp.var two-pass semantics ----
__global__ void bn_stats_kernel(const float* __restrict__ x,
                                float* __restrict__ mean_out,
                                float* __restrict__ r_out,
                                int N, int C, int HW)
{
    int c = blockIdx.x;
    int tx = threadIdx.x;
    __shared__ float red[256];
    __shared__ float s_m;
    float inv = 1.f / (float)(N * HW);

    float s = 0.f;
    for (int n = 0; n < N; ++n) {
        const float* p = x + ((size_t)n * C + c) * HW;
        for (int i = tx; i < HW; i += 256) s += p[i];
    }
    red[tx] = s;
    __syncthreads();
    for (int o = 128; o > 0; o >>= 1) {
        if (tx < o) red[tx] += red[tx + o];
        __syncthreads();
    }
    if (tx == 0) s_m = red[0] * inv;
    __syncthreads();
    float m = s_m;

    float s2 = 0.f;
    for (int n = 0; n < N; ++n) {
        const float* p = x + ((size_t)n * C + c) * HW;
        for (int i = tx; i < HW; i += 256) {
            float d = __fsub_rn(p[i], m);
            s2 += __fmul_rn(d, d);
        }
    }
    red[tx] = s2;
    __syncthreads();
    for (int o = 128; o > 0; o >>= 1) {
        if (tx < o) red[tx] += red[tx + o];
        __syncthreads();
    }
    if (tx == 0) {
        float var = red[0] * inv;
        mean_out[c] = m;
        r_out[c] = __fdiv_rn(1.0f, __fsqrt_rn(__fadd_rn(var, BN_EPS)));
    }
}

__device__ __forceinline__ float bnrelu_apply(float v, float m, float r, float g, float b)
{
    float t = __fsub_rn(v, m);
    t = __fmul_rn(t, r);
    t = __fmul_rn(t, g);
    t = __fadd_rn(t, b);
    return fmaxf(t, 0.f);
}

// ================= conv 3x3 s1 p1, 256->256, 32x32, BN+ReLU on input =================
// Tile 64co x (8x16)px, 256 thr, 4co x 8px (4 pairs) per thread. FFMA2 inner loop.
__global__ void __launch_bounds__(256)
conv3x3_f2(const float* __restrict__ in, const float* __restrict__ wgt,
           const float* __restrict__ bias,
           const float* __restrict__ bmean, const float* __restrict__ br,
           const float* __restrict__ bg, const float* __restrict__ bb,
           float* __restrict__ out)
{
    constexpr int CI = 4, KC = 36, W2S = 37, PH = 10, PW = 18;
    __shared__ float s_in[CI * PH * PW];
    __shared__ float s_w2[64 * W2S * 2];

    int n   = blockIdx.x >> 3;
    int t   = blockIdx.x & 7;
    int oh0 = (t >> 1) * 8, ow0 = (t & 1) * 16;
    int co0 = blockIdx.y * 64;
    int tx = threadIdx.x, c = tx & 15, r = tx >> 4;
    int row = r >> 1, owl0 = (r & 1) * 8;

    f2 acc[4][4];
#pragma unroll
    for (int j = 0; j < 4; ++j)
#pragma unroll
        for (int pp = 0; pp < 4; ++pp) acc[j][pp] = 0ull;

    int ihb = oh0 - 1, iwb = ow0 - 1;

#pragma unroll 1
    for (int ci0 = 0; ci0 < 256; ci0 += CI) {
        __syncthreads();
#pragma unroll 1
        for (int idx = tx; idx < CI * PH * PW; idx += 256) {
            int ci = idx / (PH * PW);
            int rem = idx - ci * (PH * PW);
            int lh = rem / PW, lw = rem - lh * PW;
            int ih = ihb + lh, iw = iwb + lw;
            int cg = ci0 + ci;
            float v = 0.f;
            if ((unsigned)ih < 32u && (unsigned)iw < 32u) {
                v = in[(((size_t)n * 256 + cg) * 32 + ih) * 32 + iw];
                v = bnrelu_apply(v, bmean[cg], br[cg], bg[cg], bb[cg]);
            }
            s_in[idx] = v;
        }
#pragma unroll 1
        for (int idx = tx; idx < 64 * KC; idx += 256) {
            int co = idx / KC, k = idx - co * KC;
            int ci = k / 9, kk = k - ci * 9;
            float w = wgt[((size_t)(co0 + co) * 256 + ci0 + ci) * 9 + kk];
            s_w2[(co * W2S + k) * 2]     = w;
            s_w2[(co * W2S + k) * 2 + 1] = w;
        }
        __syncthreads();
#pragma unroll
        for (int ci = 0; ci < CI; ++ci) {
#pragma unroll
            for (int kh = 0; kh < 3; ++kh) {
                const float* bp = &s_in[ci * PH * PW + (row + kh) * PW + owl0];
                f2 P[5];
#pragma unroll
                for (int q = 0; q < 5; ++q) P[q] = lds2(bp + 2 * q);
                float v[10];
#pragma unroll
                for (int q = 0; q < 5; ++q) upk2(P[q], v[2 * q], v[2 * q + 1]);
                f2 M[4];
#pragma unroll
                for (int pp = 0; pp < 4; ++pp) M[pp] = pk2(v[1 + 2 * pp], v[2 + 2 * pp]);
                int kbase = ci * 9 + kh * 3;
#pragma unroll
                for (int kw = 0; kw < 3; ++kw) {
                    int k = kbase + kw;
                    f2 wv[4];
#pragma unroll
                    for (int j = 0; j < 4; ++j) wv[j] = lds2(&s_w2[((c + 16 * j) * W2S + k) * 2]);
#pragma unroll
                    for (int j = 0; j < 4; ++j)
#pragma unroll
                        for (int pp = 0; pp < 4; ++pp) {
                            f2 iv = (kw == 0) ? P[pp] : ((kw == 1) ? M[pp] : P[pp + 1]);
                            acc[j][pp] = fma2(wv[j], iv, acc[j][pp]);
                        }
                }
            }
        }
    }
    int oh = oh0 + row;
#pragma unroll
    for (int j = 0; j < 4; ++j) {
        int co = co0 + c + 16 * j;
        float bv = bias[co];
        size_t base = (((size_t)n * 256 + co) * 32 + oh) * 32 + ow0 + owl0;
#pragma unroll
        for (int pp = 0; pp < 4; ++pp) {
            float lo, hi; upk2(acc[j][pp], lo, hi);
            out[base + 2 * pp]     = __fadd_rn(lo, bv);
            out[base + 2 * pp + 1] = __fadd_rn(hi, bv);
        }
    }
}

// ================= conv 1x1, 256->256, 32x32, BN+ReLU in, residual add =================
__global__ void __launch_bounds__(256)
conv1x1_f2(const float* __restrict__ in, const float* __restrict__ wgt,
           const float* __restrict__ bias,
           const float* __restrict__ bmean, const float* __restrict__ br,
           const float* __restrict__ bg, const float* __restrict__ bb,
           const float* __restrict__ res, float* __restrict__ out)
{
    constexpr int CI = 32, W2S = 33;
    __shared__ float s_in[CI * 128];
    __shared__ float s_w2[64 * W2S * 2];

    int n   = blockIdx.x >> 3;
    int t   = blockIdx.x & 7;
    int oh0 = (t >> 1) * 8, ow0 = (t & 1) * 16;
    int co0 = blockIdx.y * 64;
    int tx = threadIdx.x, c = tx & 15, r = tx >> 4;
    int row = r >> 1, owl0 = (r & 1) * 8;

    f2 acc[4][4];
#pragma unroll
    for (int j = 0; j < 4; ++j)
#pragma unroll
        for (int pp = 0; pp < 4; ++pp) acc[j][pp] = 0ull;

#pragma unroll 1
    for (int ci0 = 0; ci0 < 256; ci0 += CI) {
        __syncthreads();
#pragma unroll 1
        for (int idx = tx; idx < CI * 128; idx += 256) {
            int ci = idx >> 7, rem = idx & 127;
            int ih = oh0 + (rem >> 4), iw = ow0 + (rem & 15);
            int cg = ci0 + ci;
            float v = in[(((size_t)n * 256 + cg) * 32 + ih) * 32 + iw];
            s_in[idx] = bnrelu_apply(v, bmean[cg], br[cg], bg[cg], bb[cg]);
        }
#pragma unroll 1
        for (int idx = tx; idx < 64 * CI; idx += 256) {
            int co = idx / CI, k = idx - co * CI;
            float w = wgt[(size_t)(co0 + co) * 256 + ci0 + k];
            s_w2[(co * W2S + k) * 2]     = w;
            s_w2[(co * W2S + k) * 2 + 1] = w;
        }
        __syncthreads();
#pragma unroll 4
        for (int ci = 0; ci < CI; ++ci) {
            const float* bp = &s_in[ci * 128 + row * 16 + owl0];
            f2 P[4];
#pragma unroll
            for (int q = 0; q < 4; ++q) P[q] = lds2(bp + 2 * q);
            f2 wv[4];
#pragma unroll
            for (int j = 0; j < 4; ++j) wv[j] = lds2(&s_w2[((c + 16 * j) * W2S + ci) * 2]);
#pragma unroll
            for (int j = 0; j < 4; ++j)
#pragma unroll
                for (int pp = 0; pp < 4; ++pp)
                    acc[j][pp] = fma2(wv[j], P[pp], acc[j][pp]);
        }
    }
    int oh = oh0 + row;
#pragma unroll
    for (int j = 0; j < 4; ++j) {
        int co = co0 + c + 16 * j;
        float bv = bias[co];
        size_t base = (((size_t)n * 256 + co) * 32 + oh) * 32 + ow0 + owl0;
#pragma unroll
        for (int pp = 0; pp < 4; ++pp) {
            float lo, hi; upk2(acc[j][pp], lo, hi);
            float v0 = __fadd_rn(__fadd_rn(lo, bv), res[base + 2 * pp]);
            float v1 = __fadd_rn(__fadd_rn(hi, bv), res[base + 2 * pp + 1]);
            out[base + 2 * pp]     = v0;
            out[base + 2 * pp + 1] = v1;
        }
    }
}

// ================= conv 4x4 s2 p1 (ec1/ec2), optional BN+ReLU on input =================
template<bool BNRELU>
__global__ void __launch_bounds__(256)
conv4x4s2_f2(const float* __restrict__ in, const float* __restrict__ wgt,
             const float* __restrict__ bias,
             const float* __restrict__ bmean, const float* __restrict__ br,
             const float* __restrict__ bg, const float* __restrict__ bb,
             float* __restrict__ out,
             int N, int Cin, int Hin, int Win, int Cout, int Hout, int Wout)
{
    constexpr int CI = 4, KC = 64, W2S = 65, PH = 18, PW = 34;
    __shared__ float s_in[CI * PH * PW];
    __shared__ float s_w2[64 * W2S * 2];

    int tilesW = Wout / 16, tilesH = Hout / 8;
    int tpi = tilesW * tilesH;
    int n = blockIdx.x / tpi;
    int t = blockIdx.x % tpi;
    int oh0 = (t / tilesW) * 8, ow0 = (t % tilesW) * 16;
    int co0 = blockIdx.y * 64;
    int tx = threadIdx.x, c = tx & 15, r = tx >> 4;
    int row = r >> 1, owl0 = (r & 1) * 8;

    f2 acc[4][4];
#pragma unroll
    for (int j = 0; j < 4; ++j)
#pragma unroll
        for (int pp = 0; pp < 4; ++pp) acc[j][pp] = 0ull;

    int ihb = oh0 * 2 - 1, iwb = ow0 * 2 - 1;

#pragma unroll 1
    for (int ci0 = 0; ci0 < Cin; ci0 += CI) {
        __syncthreads();
#pragma unroll 1
        for (int idx = tx; idx < CI * PH * PW; idx += 256) {
            int ci = idx / (PH * PW);
            int rem = idx - ci * (PH * PW);
            int lh = rem / PW, lw = rem - lh * PW;
            int ih = ihb + lh, iw = iwb + lw;
            int cg = ci0 + ci;
            float v = 0.f;
            if (cg < Cin && (unsigned)ih < (unsigned)Hin && (unsigned)iw < (unsigned)Win) {
                v = in[(((size_t)n * Cin + cg) * Hin + ih) * Win + iw];
                if (BNRELU) v = bnrelu_apply(v, bmean[cg], br[cg], bg[cg], bb[cg]);
            }
            s_in[idx] = v;
        }
#pragma unroll 1
        for (int idx = tx; idx < 64 * KC; idx += 256) {
            int co = idx / KC, k = idx - co * KC;
            int ci = k >> 4, kk = k & 15;
            int cg = ci0 + ci;
            float w = (cg < Cin) ? wgt[((size_t)(co0 + co) * Cin + cg) * 16 + kk] : 0.f;
            s_w2[(co * W2S + k) * 2]     = w;
            s_w2[(co * W2S + k) * 2 + 1] = w;
        }
        __syncthreads();
#pragma unroll
        for (int ci = 0; ci < CI; ++ci) {
#pragma unroll
            for (int kh = 0; kh < 4; ++kh) {
                const float* bp = &s_in[ci * PH * PW + (row * 2 + kh) * PW + owl0 * 2];
                float v[18];
#pragma unroll
                for (int q = 0; q < 9; ++q) {
                    f2 Q = lds2(bp + 2 * q);
                    upk2(Q, v[2 * q], v[2 * q + 1]);
                }
#pragma unroll
                for (int kw = 0; kw < 4; ++kw) {
                    int k = ci * 16 + kh * 4 + kw;
                    f2 m[4];
#pragma unroll
                    for (int pp = 0; pp < 4; ++pp) m[pp] = pk2(v[kw + 4 * pp], v[kw + 4 * pp + 2]);
                    f2 wv[4];
#pragma unroll
                    for (int j = 0; j < 4; ++j) wv[j] = lds2(&s_w2[((c + 16 * j) * W2S + k) * 2]);
#pragma unroll
                    for (int j = 0; j < 4; ++j)
#pragma unroll
                        for (int pp = 0; pp < 4; ++pp)
                            acc[j][pp] = fma2(wv[j], m[pp], acc[j][pp]);
                }
            }
        }
    }
    int oh = oh0 + row;
#pragma unroll
    for (int j = 0; j < 4; ++j) {
        int co = co0 + c + 16 * j;
        float bv = bias[co];
        size_t base = (((size_t)n * Cout + co) * Hout + oh) * Wout + ow0 + owl0;
#pragma unroll
        for (int pp = 0; pp < 4; ++pp) {
            float lo, hi; upk2(acc[j][pp], lo, hi);
            out[base + 2 * pp]     = __fadd_rn(lo, bv);
            out[base + 2 * pp + 1] = __fadd_rn(hi, bv);
        }
    }
}

// ================= transposed conv 4x4 s2 p1, 256->256, BN+ReLU on input =================
__global__ void __launch_bounds__(256)
convT4x4_f2(const float* __restrict__ in, const float* __restrict__ wgt,
            const float* __restrict__ bias,
            const float* __restrict__ bmean, const float* __restrict__ br,
            const float* __restrict__ bg, const float* __restrict__ bb,
            float* __restrict__ out,
            int N, int Cin, int Hin, int Win, int Cout, int Hout, int Wout)
{
    constexpr int CI = 4, KC = 64, W2S = 65, PH = 6, PW = 10;
    __shared__ float s_in[CI * PH * PW + 2];
    __shared__ float s_w2[64 * W2S * 2];

    int tilesW = Wout / 16, tilesH = Hout / 8;
    int tpi = tilesW * tilesH;
    int n = blockIdx.x / tpi;
    int t = blockIdx.x % tpi;
    int oh0 = (t / tilesW) * 8, ow0 = (t % tilesW) * 16;
    int co0 = blockIdx.y * 64;
    int tx = threadIdx.x, c = tx & 15, r = tx >> 4;
    int row = r >> 1, par = r & 1;

    int ih0 = (oh0 >> 1) - 1, iw0 = (ow0 >> 1) - 1;
    int khp = (row + 1) & 1;
    int kwp = 1 - par;

    f2 acc[4][4];
#pragma unroll
    for (int j = 0; j < 4; ++j)
#pragma unroll
        for (int pp = 0; pp < 4; ++pp) acc[j][pp] = 0ull;

#pragma unroll 1
    for (int ci0 = 0; ci0 < Cin; ci0 += CI) {
        __syncthreads();
#pragma unroll 1
        for (int idx = tx; idx < CI * PH * PW; idx += 256) {
            int ci = idx / (PH * PW);
            int rem = idx - ci * (PH * PW);
            int lh = rem / PW, lw = rem - lh * PW;
            int ih = ih0 + lh, iw = iw0 + lw;
            int cg = ci0 + ci;
            float v = 0.f;
            if ((unsigned)ih < (unsigned)Hin && (unsigned)iw < (unsigned)Win) {
                v = in[(((size_t)n * Cin + cg) * Hin + ih) * Win + iw];
                v = bnrelu_apply(v, bmean[cg], br[cg], bg[cg], bb[cg]);
            }
            s_in[idx] = v;
        }
#pragma unroll 1
        for (int idx = tx; idx < 64 * KC; idx += 256) {
            int co = idx / KC, k = idx - co * KC;
            int ci = k >> 4, kk = k & 15;
            float w = wgt[(((size_t)(ci0 + ci) * Cout + co0 + co) << 4) + kk];
            s_w2[(co * W2S + k) * 2]     = w;
            s_w2[(co * W2S + k) * 2 + 1] = w;
        }
        __syncthreads();
#pragma unroll
        for (int ci = 0; ci < CI; ++ci) {
#pragma unroll
            for (int a = 0; a < 2; ++a) {
                int kh  = khp + 2 * a;
                int ihl = ((row + 1) >> 1) + 1 - a;
                int s   = ci * PH * PW + ihl * PW + par;
                int e   = s & ~1;
                int o   = s - e;
                float v[12];
#pragma unroll
                for (int q = 0; q < 6; ++q) {
                    f2 Q = lds2(&s_in[e + 2 * q]);
                    upk2(Q, v[2 * q], v[2 * q + 1]);
                }
#pragma unroll
                for (int b = 0; b < 2; ++b) {
                    int kw = kwp + 2 * b;
                    int k  = ci * 16 + kh * 4 + kw;
                    f2 m[4];
#pragma unroll
                    for (int pp = 0; pp < 4; ++pp)
                        m[pp] = pk2(v[o + 1 - b + 2 * pp], v[o + 1 - b + 2 * pp + 1]);
                    f2 wv[4];
#pragma unroll
                    for (int j = 0; j < 4; ++j) wv[j] = lds2(&s_w2[((c + 16 * j) * W2S + k) * 2]);
#pragma unroll
                    for (int j = 0; j < 4; ++j)
#pragma unroll
                        for (int pp = 0; pp < 4; ++pp)
                            acc[j][pp] = fma2(wv[j], m[pp], acc[j][pp]);
                }
            }
        }
    }
    int oh = oh0 + row;
#pragma unroll
    for (int j = 0; j < 4; ++j) {
        int co = co0 + c + 16 * j;
        float bv = bias[co];
        size_t base = (((size_t)n * Cout + co) * Hout + oh) * Wout + ow0 + par;
#pragma unroll
        for (int pp = 0; pp < 4; ++pp) {
            float lo, hi; upk2(acc[j][pp], lo, hi);
            out[base + 4 * pp]     = __fadd_rn(lo, bv);
            out[base + 4 * pp + 2] = __fadd_rn(hi, bv);
        }
    }
}

// ---------------- final transposed conv to 3 channels (scalar; small) ----------------
__global__ void __launch_bounds__(256)
convT_out_kernel(const float* __restrict__ in, const float* __restrict__ wgt,
                 const float* __restrict__ bias,
                 const float* __restrict__ bmean, const float* __restrict__ br,
                 const float* __restrict__ bg, const float* __restrict__ bb,
                 float* __restrict__ out,
                 int N, int Cin, int Hin, int Win, int Hout, int Wout)
{
    constexpr int CI = 16;
    __shared__ float s_in[CI * 100];
    __shared__ float s_w[CI * 48];
    int tilesW = Wout / 16;
    int tpi = tilesW * (Hout / 16);
    int n  = blockIdx.x / tpi;
    int t  = blockIdx.x % tpi;
    int oh0 = (t / tilesW) * 16, ow0 = (t % tilesW) * 16;
    int tx  = threadIdx.x;
    int row = tx >> 4, col = tx & 15;
    int oh = oh0 + row, ow = ow0 + col;
    int khp = (oh + 1) & 1, kwp = (ow + 1) & 1;
    int ih0 = (oh0 >> 1) - 1, iw0 = (ow0 >> 1) - 1;
    float acc[3] = {0.f, 0.f, 0.f};

#pragma unroll 1
    for (int ci0 = 0; ci0 < Cin; ci0 += CI) {
        __syncthreads();
#pragma unroll 1
        for (int idx = tx; idx < CI * 100; idx += 256) {
            int ci  = idx / 100;
            int rem = idx - ci * 100;
            int lh  = rem / 10, lw = rem - lh * 10;
            int ih  = ih0 + lh, iw = iw0 + lw;
            float v = 0.f;
            if ((unsigned)ih < (unsigned)Hin && (unsigned)iw < (unsigned)Win) {
                int cg = ci0 + ci;
                v = in[(((size_t)n * Cin + cg) * Hin + ih) * Win + iw];
                v = bnrelu_apply(v, bmean[cg], br[cg], bg[cg], bb[cg]);
            }
            s_in[idx] = v;
        }
#pragma unroll 1
        for (int idx = tx; idx < CI * 48; idx += 256) {
            int ci  = idx / 48;
            int rem = idx - ci * 48;
            s_w[idx] = wgt[(size_t)(ci0 + ci) * 48 + rem];
        }
        __syncthreads();
#pragma unroll 2
        for (int ci = 0; ci < CI; ++ci) {
#pragma unroll
            for (int a = 0; a < 2; ++a) {
                int ihl = ((oh + 1) >> 1) - a - ih0;
                int kh  = khp + 2 * a;
#pragma unroll
                for (int b = 0; b < 2; ++b) {
                    int iwl = ((ow + 1) >> 1) - b - iw0;
                    int kw  = kwp + 2 * b;
                    float iv = s_in[ci * 100 + ihl * 10 + iwl];
#pragma unroll
                    for (int co = 0; co < 3; ++co)
                        acc[co] = fmaf(s_w[ci * 48 + co * 16 + kh * 4 + kw], iv, acc[co]);
                }
            }
        }
    }
#pragma unroll
    for (int co = 0; co < 3; ++co)
        out[(((size_t)n * 3 + co) * Hout + oh) * Wout + ow] = __fadd_rn(acc[co], bias[co]);
}

// ---------------- VQ (reference fp32 numerics, unchanged from passing R7) ----------------
__global__ void cnorm_kernel(const float* __restrict__ cb, float* __restrict__ cn)
{
    int k = blockIdx.x * blockDim.x + threadIdx.x;
    if (k < 512) {
        const float* p = cb + (size_t)k * 256;
        float acc = 0.f;
#pragma unroll 4
        for (int d = 0; d < 256; ++d)
            acc = __fadd_rn(acc, __fmul_rn(p[d], p[d]));
        cn[k] = acc;
    }
}

__global__ void __launch_bounds__(256)
vq_argmin_kernel(const float* __restrict__ z, const float* __restrict__ cb,
                 const float* __restrict__ cn, int* __restrict__ q)
{
    __shared__ float s_z[32 * 257];
    __shared__ float s_Z[32];
    __shared__ float s_bd[256];
    __shared__ int   s_bi[256];
    int nh = blockIdx.x;
    int n = nh >> 5, h = nh & 31;
    int tx = threadIdx.x;
    size_t zb = (size_t)n * 262144 + (size_t)h * 32;
#pragma unroll 1
    for (int idx = tx; idx < 256 * 32; idx += 256) {
        int d = idx >> 5, w = idx & 31;
        s_z[w * 257 + d] = 2.0f * z[zb + (size_t)d * 1024 + w];
    }
    __syncthreads();
    if (tx < 32) {
        const float* zr = s_z + tx * 257;
        float acc = 0.f;
#pragma unroll 4
        for (int d = 0; d < 256; ++d) {
            float zv = 0.5f * zr[d];
            acc = __fadd_rn(acc, __fmul_rn(zv, zv));
        }
        s_Z[tx] = acc;
    }
    __syncthreads();

    int m = tx & 31, g = tx >> 5;
    const float* zr = s_z + m * 257;
    float Zm = s_Z[m];
    float best = 3.4028235e38f;
    int bi = 0;
#pragma unroll 1
    for (int t = 0; t < 64; t += 2) {
        int k0 = g + 8 * t;
        int k1 = k0 + 8;
        const float* c0 = cb + (size_t)k0 * 256;
        const float* c1 = cb + (size_t)k1 * 256;
        float A = 0.f, B = 0.f;
#pragma unroll 4
        for (int d = 0; d < 256; ++d) {
            float zv = zr[d];
            A = fmaf(zv, c0[d], A);
            B = fmaf(zv, c1[d], B);
        }
        float t0 = __fadd_rn(__fsub_rn(Zm, A), cn[k0]);
        float t1 = __fadd_rn(__fsub_rn(Zm, B), cn[k1]);
        if (t0 < best) { best = t0; bi = k0; }
        if (t1 < best) { best = t1; bi = k1; }
    }
    s_bd[g * 32 + m] = best;
    s_bi[g * 32 + m] = bi;
    __syncthreads();
    if (tx < 32) {
        float bb = s_bd[tx];
        int   ii = s_bi[tx];
#pragma unroll
        for (int gg = 1; gg < 8; ++gg) {
            float dd = s_bd[gg * 32 + tx];
            int   jj = s_bi[gg * 32 + tx];
            if (dd < bb || (dd == bb && jj < ii)) { bb = dd; ii = jj; }
        }
        q[nh * 32 + tx] = ii;
    }
}

__global__ void vq_gather_kernel(const int* __restrict__ q, const float* __restrict__ cb,
                                 float* __restrict__ zq)
{
    __shared__ int s_q[32];
    int nh = blockIdx.x;
    int n = nh >> 5, h = nh & 31;
    int tx = threadIdx.x;
    if (tx < 32) s_q[tx] = q[nh * 32 + tx];
    __syncthreads();
    size_t zb = (size_t)n * 262144 + (size_t)h * 32;
#pragma unroll 1
    for (int idx = tx; idx < 256 * 32; idx += 256) {
        int d = idx >> 5, w = idx & 31;
        zq[zb + (size_t)d * 1024 + w] = cb[(size_t)s_q[w] * 256 + d];
    }
}

// ---------------- host ----------------
static void run_resblock(const float* X, float* T, float* Y,
                         const float* bn1g, const float* bn1b,
                         const float* c3w, const float* c3b,
                         const float* bn2g, const float* bn2b,
                         const float* c1w, const float* c1b,
                         float* mn, float* rr)
{
    dim3 grid(16 * 8, 4);
    bn_stats_kernel<<<256, 256>>>(X, mn, rr, 16, 256, 1024);
    conv3x3_f2<<<grid, 256>>>(X, c3w, c3b, mn, rr, bn1g, bn1b, T);
    bn_stats_kernel<<<256, 256>>>(T, mn, rr, 16, 256, 1024);
    conv1x1_f2<<<grid, 256>>>(T, c1w, c1b, mn, rr, bn2g, bn2b, X, Y);
}

extern "C" void kernel_launch(void* const* d_in, const int* in_sizes, int n_in,
                              void* d_out, int out_size)
{
    (void)in_sizes; (void)n_in; (void)out_size;
    const float* x        = (const float*)d_in[0];
    const float* ec1_w    = (const float*)d_in[1];
    const float* ec1_b    = (const float*)d_in[2];
    const float* ebn1_g   = (const float*)d_in[3];
    const float* ebn1_b   = (const float*)d_in[4];
    const float* ec2_w    = (const float*)d_in[5];
    const float* ec2_b    = (const float*)d_in[6];
    const float* rb_bn1_g = (const float*)d_in[7];
    const float* rb_bn1_b = (const float*)d_in[8];
    const float* rb_c3_w  = (const float*)d_in[9];
    const float* rb_c3_b  = (const float*)d_in[10];
    const float* rb_bn2_g = (const float*)d_in[11];
    const float* rb_bn2_b = (const float*)d_in[12];
    const float* rb_c1_w  = (const float*)d_in[13];
    const float* rb_c1_b  = (const float*)d_in[14];
    const float* dbn1_g   = (const float*)d_in[15];
    const float* dbn1_b   = (const float*)d_in[16];
    const float* dct1_w   = (const float*)d_in[17];
    const float* dct1_b   = (const float*)d_in[18];
    const float* dbn2_g   = (const float*)d_in[19];
    const float* dbn2_b   = (const float*)d_in[20];
    const float* dct2_w   = (const float*)d_in[21];
    const float* dct2_b   = (const float*)d_in[22];
    const float* codebook = (const float*)d_in[23];

    float *A64, *Ba, *Bb, *Bc, *mn, *rr, *cn;
    int* q;
    cudaGetSymbolAddress((void**)&A64, g_A64);
    cudaGetSymbolAddress((void**)&Ba,  g_B32a);
    cudaGetSymbolAddress((void**)&Bb,  g_B32b);
    cudaGetSymbolAddress((void**)&Bc,  g_B32c);
    cudaGetSymbolAddress((void**)&mn,  g_mean);
    cudaGetSymbolAddress((void**)&rr,  g_r);
    cudaGetSymbolAddress((void**)&cn,  g_cnorm);
    cudaGetSymbolAddress((void**)&q,   g_q);

    float* out   = (float*)d_out;
    float* x_rec = out;
    float* z_e   = out + 786432;
    float* z_q   = z_e + 4194304;

    // encoder
    conv4x4s2_f2<false><<<dim3(16 * 32, 4), 256>>>(
        x, ec1_w, ec1_b, nullptr, nullptr, nullptr, nullptr, A64,
        16, 3, 128, 128, 256, 64, 64);
    bn_stats_kernel<<<256, 256>>>(A64, mn, rr, 16, 256, 4096);
    conv4x4s2_f2<true><<<dim3(16 * 8, 4), 256>>>(
        A64, ec2_w, ec2_b, mn, rr, ebn1_g, ebn1_b, Ba,
        16, 256, 64, 64, 256, 32, 32);

    const size_t W3 = (size_t)256 * 256 * 9;
    const size_t W1 = (size_t)256 * 256;
    run_resblock(Ba, Bb, Bc, rb_bn1_g + 0, rb_bn1_b + 0, rb_c3_w + 0 * W3, rb_c3_b + 0,
                 rb_bn2_g + 0, rb_bn2_b + 0, rb_c1_w + 0 * W1, rb_c1_b + 0, mn, rr);
    run_resblock(Bc, Bb, z_e, rb_bn1_g + 256, rb_bn1_b + 256, rb_c3_w + 1 * W3, rb_c3_b + 256,
                 rb_bn2_g + 256, rb_bn2_b + 256, rb_c1_w + 1 * W1, rb_c1_b + 256, mn, rr);

    // VQ
    cnorm_kernel<<<2, 256>>>(codebook, cn);
    vq_argmin_kernel<<<512, 256>>>(z_e, codebook, cn, q);
    vq_gather_kernel<<<512, 256>>>(q, codebook, z_q);

    // decoder
    run_resblock(z_e, Ba, Bb, rb_bn1_g + 512, rb_bn1_b + 512, rb_c3_w + 2 * W3, rb_c3_b + 512,
                 rb_bn2_g + 512, rb_bn2_b + 512, rb_c1_w + 2 * W1, rb_c1_b + 512, mn, rr);
    run_resblock(Bb, Bc, Ba, rb_bn1_g + 768, rb_bn1_b + 768, rb_c3_w + 3 * W3, rb_c3_b + 768,
                 rb_bn2_g + 768, rb_bn2_b + 768, rb_c1_w + 3 * W1, rb_c1_b + 768, mn, rr);

    bn_stats_kernel<<<256, 256>>>(Ba, mn, rr, 16, 256, 1024);
    convT4x4_f2<<<dim3(16 * 32, 4), 256>>>(
        Ba, dct1_w, dct1_b, mn, rr, dbn1_g, dbn1_b, A64,
        16, 256, 32, 32, 256, 64, 64);
    bn_stats_kernel<<<256, 256>>>(A64, mn, rr, 16, 256, 4096);
    convT_out_kernel<<<16 * 64, 256>>>(
        A64, dct2_w, dct2_b, mn, rr, dbn2_g, dbn2_b, x_rec,
        16, 256, 64, 64, 128, 128);
}

// round 14
// speedup vs baseline: 1.1040x; 1.1040x over previous
#include <cuda_runtime.h>
#include <cstdint>

#define BN_EPS 1e-5f

static constexpr size_t SZ64 = (size_t)16 * 256 * 64 * 64;
static constexpr size_t SZ32 = (size_t)16 * 256 * 32 * 32;

__device__ float g_A64[SZ64];
__device__ float g_B32a[SZ32];
__device__ float g_B32b[SZ32];
__device__ float g_B32c[SZ32];
__device__ float g_mean[256];
__device__ float g_r[256];
__device__ float g_cnorm[512];
__device__ int   g_q[16384];

// ---- BN batch stats: mean + r = 1/sqrt(var+eps), jnp.var two-pass semantics ----
__global__ void bn_stats_kernel(const float* __restrict__ x,
                                float* __restrict__ mean_out,
                                float* __restrict__ r_out,
                                int N, int C, int HW)
{
    int c = blockIdx.x;
    int tx = threadIdx.x;
    __shared__ float red[256];
    __shared__ float s_m;
    float inv = 1.f / (float)(N * HW);

    float s = 0.f;
    for (int n = 0; n < N; ++n) {
        const float* p = x + ((size_t)n * C + c) * HW;
        for (int i = tx; i < HW; i += 256) s += p[i];
    }
    red[tx] = s;
    __syncthreads();
    for (int o = 128; o > 0; o >>= 1) {
        if (tx < o) red[tx] += red[tx + o];
        __syncthreads();
    }
    if (tx == 0) s_m = red[0] * inv;
    __syncthreads();
    float m = s_m;

    float s2 = 0.f;
    for (int n = 0; n < N; ++n) {
        const float* p = x + ((size_t)n * C + c) * HW;
        for (int i = tx; i < HW; i += 256) {
            float d = __fsub_rn(p[i], m);
            s2 += __fmul_rn(d, d);
        }
    }
    red[tx] = s2;
    __syncthreads();
    for (int o = 128; o > 0; o >>= 1) {
        if (tx < o) red[tx] += red[tx + o];
        __syncthreads();
    }
    if (tx == 0) {
        float var = red[0] * inv;
        mean_out[c] = m;
        r_out[c] = __fdiv_rn(1.0f, __fsqrt_rn(__fadd_rn(var, BN_EPS)));
    }
}

__device__ __forceinline__ float bnrelu_apply(float v, float m, float r, float g, float b)
{
    float t = __fsub_rn(v, m);
    t = __fmul_rn(t, r);
    t = __fmul_rn(t, g);
    t = __fadd_rn(t, b);
    return fmaxf(t, 0.f);
}

// ================= conv 3x3 s1 p1, 256->256, 32x32, BN+ReLU on input =================
// 32co x (8x16)px per block (1024 blocks: 99% SM balance), 256 thr,
// 2co x 8px per thread, input rows loaded once per (ci,kh) and reused across kw.
__global__ void __launch_bounds__(256)
conv3x3_v2(const float* __restrict__ in, const float* __restrict__ wgt,
           const float* __restrict__ bias,
           const float* __restrict__ bmean, const float* __restrict__ br,
           const float* __restrict__ bg, const float* __restrict__ bb,
           float* __restrict__ out)
{
    constexpr int CI = 8, KC = 72, WS = 73, PH = 10, PW = 18;
    __shared__ float s_in[CI * PH * PW];
    __shared__ float s_w[32 * WS];

    int n   = blockIdx.x >> 3;
    int t   = blockIdx.x & 7;
    int oh0 = (t >> 1) * 8, ow0 = (t & 1) * 16;
    int co0 = blockIdx.y * 32;
    int tx = threadIdx.x, c = tx & 15, r = tx >> 4;
    int row = r >> 1, owl0 = (r & 1) * 8;

    float acc[2][8];
#pragma unroll
    for (int j = 0; j < 2; ++j)
#pragma unroll
        for (int p = 0; p < 8; ++p) acc[j][p] = 0.f;

    int ihb = oh0 - 1, iwb = ow0 - 1;

#pragma unroll 1
    for (int ci0 = 0; ci0 < 256; ci0 += CI) {
        __syncthreads();
#pragma unroll 1
        for (int idx = tx; idx < CI * PH * PW; idx += 256) {
            int ci = idx / (PH * PW);
            int rem = idx - ci * (PH * PW);
            int lh = rem / PW, lw = rem - lh * PW;
            int ih = ihb + lh, iw = iwb + lw;
            int cg = ci0 + ci;
            float v = 0.f;
            if ((unsigned)ih < 32u && (unsigned)iw < 32u) {
                v = in[(((size_t)n * 256 + cg) * 32 + ih) * 32 + iw];
                v = bnrelu_apply(v, bmean[cg], br[cg], bg[cg], bb[cg]);
            }
            s_in[idx] = v;
        }
#pragma unroll 1
        for (int idx = tx; idx < 32 * KC; idx += 256) {
            int co = idx / KC, k = idx - co * KC;
            int ci = k / 9, kk = k - ci * 9;
            s_w[co * WS + k] = wgt[((size_t)(co0 + co) * 256 + ci0 + ci) * 9 + kk];
        }
        __syncthreads();
#pragma unroll
        for (int ci = 0; ci < CI; ++ci) {
#pragma unroll
            for (int kh = 0; kh < 3; ++kh) {
                const float* bp = &s_in[ci * PH * PW + (row + kh) * PW + owl0];  // even addr
                float v[10];
#pragma unroll
                for (int q = 0; q < 5; ++q) {
                    float2 Q = *(const float2*)(bp + 2 * q);
                    v[2 * q] = Q.x; v[2 * q + 1] = Q.y;
                }
                int kbase = ci * 9 + kh * 3;
#pragma unroll
                for (int kw = 0; kw < 3; ++kw) {
                    int k = kbase + kw;
                    float wv[2];
#pragma unroll
                    for (int j = 0; j < 2; ++j) wv[j] = s_w[(c + 16 * j) * WS + k];
#pragma unroll
                    for (int j = 0; j < 2; ++j)
#pragma unroll
                        for (int p = 0; p < 8; ++p)
                            acc[j][p] = fmaf(wv[j], v[kw + p], acc[j][p]);
                }
            }
        }
    }
    int oh = oh0 + row;
#pragma unroll
    for (int j = 0; j < 2; ++j) {
        int co = co0 + c + 16 * j;
        float bv = bias[co];
        size_t base = (((size_t)n * 256 + co) * 32 + oh) * 32 + ow0 + owl0;
#pragma unroll
        for (int p = 0; p < 8; ++p)
            out[base + p] = __fadd_rn(acc[j][p], bv);
    }
}

// ================= conv 1x1, 256->256, 32x32, BN+ReLU in, residual add =================
__global__ void __launch_bounds__(256)
conv1x1_v2(const float* __restrict__ in, const float* __restrict__ wgt,
           const float* __restrict__ bias,
           const float* __restrict__ bmean, const float* __restrict__ br,
           const float* __restrict__ bg, const float* __restrict__ bb,
           const float* __restrict__ res, float* __restrict__ out)
{
    constexpr int CI = 32, WS = 33;
    __shared__ float s_in[CI * 128];
    __shared__ float s_w[64 * WS];

    int n   = blockIdx.x >> 3;
    int t   = blockIdx.x & 7;
    int oh0 = (t >> 1) * 8, ow0 = (t & 1) * 16;
    int co0 = blockIdx.y * 64;
    int tx = threadIdx.x, c = tx & 15, r = tx >> 4;
    int row = r >> 1, owl0 = (r & 1) * 8;

    float acc[4][8];
#pragma unroll
    for (int j = 0; j < 4; ++j)
#pragma unroll
        for (int p = 0; p < 8; ++p) acc[j][p] = 0.f;

#pragma unroll 1
    for (int ci0 = 0; ci0 < 256; ci0 += CI) {
        __syncthreads();
#pragma unroll 1
        for (int idx = tx; idx < CI * 128; idx += 256) {
            int ci = idx >> 7, rem = idx & 127;
            int ih = oh0 + (rem >> 4), iw = ow0 + (rem & 15);
            int cg = ci0 + ci;
            float v = in[(((size_t)n * 256 + cg) * 32 + ih) * 32 + iw];
            s_in[idx] = bnrelu_apply(v, bmean[cg], br[cg], bg[cg], bb[cg]);
        }
#pragma unroll 1
        for (int idx = tx; idx < 64 * CI; idx += 256) {
            int co = idx / CI, k = idx - co * CI;
            s_w[co * WS + k] = wgt[(size_t)(co0 + co) * 256 + ci0 + k];
        }
        __syncthreads();
#pragma unroll 4
        for (int ci = 0; ci < CI; ++ci) {
            const float* bp = &s_in[ci * 128 + row * 16 + owl0];  // even addr
            float v[8];
#pragma unroll
            for (int q = 0; q < 4; ++q) {
                float2 Q = *(const float2*)(bp + 2 * q);
                v[2 * q] = Q.x; v[2 * q + 1] = Q.y;
            }
            float wv[4];
#pragma unroll
            for (int j = 0; j < 4; ++j) wv[j] = s_w[(c + 16 * j) * WS + ci];
#pragma unroll
            for (int j = 0; j < 4; ++j)
#pragma unroll
                for (int p = 0; p < 8; ++p)
                    acc[j][p] = fmaf(wv[j], v[p], acc[j][p]);
        }
    }
    int oh = oh0 + row;
#pragma unroll
    for (int j = 0; j < 4; ++j) {
        int co = co0 + c + 16 * j;
        float bv = bias[co];
        size_t base = (((size_t)n * 256 + co) * 32 + oh) * 32 + ow0 + owl0;
#pragma unroll
        for (int p = 0; p < 8; ++p)
            out[base + p] = __fadd_rn(__fadd_rn(acc[j][p], bv), res[base + p]);
    }
}

// ================= conv 4x4 s2 p1 (ec1/ec2): 32co x (8x16)px, row reuse =================
template<bool BNRELU>
__global__ void __launch_bounds__(256)
conv4x4s2_v2(const float* __restrict__ in, const float* __restrict__ wgt,
             const float* __restrict__ bias,
             const float* __restrict__ bmean, const float* __restrict__ br,
             const float* __restrict__ bg, const float* __restrict__ bb,
             float* __restrict__ out,
             int N, int Cin, int Hin, int Win, int Cout, int Hout, int Wout)
{
    constexpr int CI = 4, KC = 64, WS = 65, PH = 18, PW = 34;
    __shared__ float s_in[CI * PH * PW];
    __shared__ float s_w[32 * WS];

    int tilesW = Wout / 16, tilesH = Hout / 8;
    int tpi = tilesW * tilesH;
    int n = blockIdx.x / tpi;
    int t = blockIdx.x % tpi;
    int oh0 = (t / tilesW) * 8, ow0 = (t % tilesW) * 16;
    int co0 = blockIdx.y * 32;
    int tx = threadIdx.x, c = tx & 15, r = tx >> 4;
    int row = r >> 1, owl0 = (r & 1) * 8;

    float acc[2][8];
#pragma unroll
    for (int j = 0; j < 2; ++j)
#pragma unroll
        for (int p = 0; p < 8; ++p) acc[j][p] = 0.f;

    int ihb = oh0 * 2 - 1, iwb = ow0 * 2 - 1;

#pragma unroll 1
    for (int ci0 = 0; ci0 < Cin; ci0 += CI) {
        __syncthreads();
#pragma unroll 1
        for (int idx = tx; idx < CI * PH * PW; idx += 256) {
            int ci = idx / (PH * PW);
            int rem = idx - ci * (PH * PW);
            int lh = rem / PW, lw = rem - lh * PW;
            int ih = ihb + lh, iw = iwb + lw;
            int cg = ci0 + ci;
            float v = 0.f;
            if (cg < Cin && (unsigned)ih < (unsigned)Hin && (unsigned)iw < (unsigned)Win) {
                v = in[(((size_t)n * Cin + cg) * Hin + ih) * Win + iw];
                if (BNRELU) v = bnrelu_apply(v, bmean[cg], br[cg], bg[cg], bb[cg]);
            }
            s_in[idx] = v;
        }
#pragma unroll 1
        for (int idx = tx; idx < 32 * KC; idx += 256) {
            int co = idx / KC, k = idx - co * KC;
            int ci = k >> 4, kk = k & 15;
            int cg = ci0 + ci;
            s_w[co * WS + k] = (cg < Cin) ? wgt[((size_t)(co0 + co) * Cin + cg) * 16 + kk] : 0.f;
        }
        __syncthreads();
#pragma unroll
        for (int ci = 0; ci < CI; ++ci) {
#pragma unroll
            for (int kh = 0; kh < 4; ++kh) {
                const float* bp = &s_in[ci * PH * PW + (row * 2 + kh) * PW + owl0 * 2];  // even
                float v[18];
#pragma unroll
                for (int q = 0; q < 9; ++q) {
                    float2 Q = *(const float2*)(bp + 2 * q);
                    v[2 * q] = Q.x; v[2 * q + 1] = Q.y;
                }
#pragma unroll
                for (int kw = 0; kw < 4; ++kw) {
                    int k = ci * 16 + kh * 4 + kw;
                    float wv[2];
#pragma unroll
                    for (int j = 0; j < 2; ++j) wv[j] = s_w[(c + 16 * j) * WS + k];
#pragma unroll
                    for (int j = 0; j < 2; ++j)
#pragma unroll
                        for (int p = 0; p < 8; ++p)
                            acc[j][p] = fmaf(wv[j], v[kw + 2 * p], acc[j][p]);
                }
            }
        }
    }
    int oh = oh0 + row;
#pragma unroll
    for (int j = 0; j < 2; ++j) {
        int co = co0 + c + 16 * j;
        float bv = bias[co];
        size_t base = (((size_t)n * Cout + co) * Hout + oh) * Wout + ow0 + owl0;
#pragma unroll
        for (int p = 0; p < 8; ++p)
            out[base + p] = __fadd_rn(acc[j][p], bv);
    }
}

// ================= transposed conv 4x4 s2 p1, 256->256, 64co, row reuse =================
__global__ void __launch_bounds__(256)
convT4x4_v2(const float* __restrict__ in, const float* __restrict__ wgt,
            const float* __restrict__ bias,
            const float* __restrict__ bmean, const float* __restrict__ br,
            const float* __restrict__ bg, const float* __restrict__ bb,
            float* __restrict__ out,
            int N, int Cin, int Hin, int Win, int Cout, int Hout, int Wout)
{
    constexpr int CI = 4, KC = 64, WS = 65, PH = 6, PW = 10;
    __shared__ float s_in[CI * PH * PW + 2];
    __shared__ float s_w[64 * WS];

    int tilesW = Wout / 16, tilesH = Hout / 8;
    int tpi = tilesW * tilesH;
    int n = blockIdx.x / tpi;
    int t = blockIdx.x % tpi;
    int oh0 = (t / tilesW) * 8, ow0 = (t % tilesW) * 16;
    int co0 = blockIdx.y * 64;
    int tx = threadIdx.x, c = tx & 15, r = tx >> 4;
    int row = r >> 1, par = r & 1;

    int ih0 = (oh0 >> 1) - 1, iw0 = (ow0 >> 1) - 1;
    int khp = (row + 1) & 1;
    int kwp = 1 - par;

    float acc[4][8];
#pragma unroll
    for (int j = 0; j < 4; ++j)
#pragma unroll
        for (int p = 0; p < 8; ++p) acc[j][p] = 0.f;

#pragma unroll 1
    for (int ci0 = 0; ci0 < Cin; ci0 += CI) {
        __syncthreads();
#pragma unroll 1
        for (int idx = tx; idx < CI * PH * PW; idx += 256) {
            int ci = idx / (PH * PW);
            int rem = idx - ci * (PH * PW);
            int lh = rem / PW, lw = rem - lh * PW;
            int ih = ih0 + lh, iw = iw0 + lw;
            int cg = ci0 + ci;
            float v = 0.f;
            if ((unsigned)ih < (unsigned)Hin && (unsigned)iw < (unsigned)Win) {
                v = in[(((size_t)n * Cin + cg) * Hin + ih) * Win + iw];
                v = bnrelu_apply(v, bmean[cg], br[cg], bg[cg], bb[cg]);
            }
            s_in[idx] = v;
        }
#pragma unroll 1
        for (int idx = tx; idx < 64 * KC; idx += 256) {
            int co = idx / KC, k = idx - co * KC;
            int ci = k >> 4, kk = k & 15;
            s_w[co * WS + k] = wgt[(((size_t)(ci0 + ci) * Cout + co0 + co) << 4) + kk];
        }
        __syncthreads();
#pragma unroll
        for (int ci = 0; ci < CI; ++ci) {
#pragma unroll
            for (int a = 0; a < 2; ++a) {
                int kh  = khp + 2 * a;
                int ihl = ((row + 1) >> 1) + 1 - a;
                int s   = ci * PH * PW + ihl * PW + par;
                int e   = s & ~1;
                int o   = s - e;
                float v[10];
#pragma unroll
                for (int q = 0; q < 5; ++q) {
                    float2 Q = *(const float2*)(&s_in[e + 2 * q]);
                    v[2 * q] = Q.x; v[2 * q + 1] = Q.y;
                }
#pragma unroll
                for (int b = 0; b < 2; ++b) {
                    int kw = kwp + 2 * b;
                    int k  = ci * 16 + kh * 4 + kw;
                    float wv[4];
#pragma unroll
                    for (int j = 0; j < 4; ++j) wv[j] = s_w[(c + 16 * j) * WS + k];
#pragma unroll
                    for (int j = 0; j < 4; ++j)
#pragma unroll
                        for (int p = 0; p < 8; ++p)
                            acc[j][p] = fmaf(wv[j], v[o + 1 - b + p], acc[j][p]);
                }
            }
        }
    }
    int oh = oh0 + row;
#pragma unroll
    for (int j = 0; j < 4; ++j) {
        int co = co0 + c + 16 * j;
        float bv = bias[co];
        size_t base = (((size_t)n * Cout + co) * Hout + oh) * Wout + ow0 + par;
#pragma unroll
        for (int p = 0; p < 8; ++p)
            out[base + 2 * p] = __fadd_rn(acc[j][p], bv);
    }
}

// ---------------- final transposed conv to 3 channels (scalar; small) ----------------
__global__ void __launch_bounds__(256)
convT_out_kernel(const float* __restrict__ in, const float* __restrict__ wgt,
                 const float* __restrict__ bias,
                 const float* __restrict__ bmean, const float* __restrict__ br,
                 const float* __restrict__ bg, const float* __restrict__ bb,
                 float* __restrict__ out,
                 int N, int Cin, int Hin, int Win, int Hout, int Wout)
{
    constexpr int CI = 16;
    __shared__ float s_in[CI * 100];
    __shared__ float s_w[CI * 48];
    int tilesW = Wout / 16;
    int tpi = tilesW * (Hout / 16);
    int n  = blockIdx.x / tpi;
    int t  = blockIdx.x % tpi;
    int oh0 = (t / tilesW) * 16, ow0 = (t % tilesW) * 16;
    int tx  = threadIdx.x;
    int row = tx >> 4, col = tx & 15;
    int oh = oh0 + row, ow = ow0 + col;
    int khp = (oh + 1) & 1, kwp = (ow + 1) & 1;
    int ih0 = (oh0 >> 1) - 1, iw0 = (ow0 >> 1) - 1;
    float acc[3] = {0.f, 0.f, 0.f};

#pragma unroll 1
    for (int ci0 = 0; ci0 < Cin; ci0 += CI) {
        __syncthreads();
#pragma unroll 1
        for (int idx = tx; idx < CI * 100; idx += 256) {
            int ci  = idx / 100;
            int rem = idx - ci * 100;
            int lh  = rem / 10, lw = rem - lh * 10;
            int ih  = ih0 + lh, iw = iw0 + lw;
            float v = 0.f;
            if ((unsigned)ih < (unsigned)Hin && (unsigned)iw < (unsigned)Win) {
                int cg = ci0 + ci;
                v = in[(((size_t)n * Cin + cg) * Hin + ih) * Win + iw];
                v = bnrelu_apply(v, bmean[cg], br[cg], bg[cg], bb[cg]);
            }
            s_in[idx] = v;
        }
#pragma unroll 1
        for (int idx = tx; idx < CI * 48; idx += 256) {
            int ci  = idx / 48;
            int rem = idx - ci * 48;
            s_w[idx] = wgt[(size_t)(ci0 + ci) * 48 + rem];
        }
        __syncthreads();
#pragma unroll 2
        for (int ci = 0; ci < CI; ++ci) {
#pragma unroll
            for (int a = 0; a < 2; ++a) {
                int ihl = ((oh + 1) >> 1) - a - ih0;
                int kh  = khp + 2 * a;
#pragma unroll
                for (int b = 0; b < 2; ++b) {
                    int iwl = ((ow + 1) >> 1) - b - iw0;
                    int kw  = kwp + 2 * b;
                    float iv = s_in[ci * 100 + ihl * 10 + iwl];
#pragma unroll
                    for (int co = 0; co < 3; ++co)
                        acc[co] = fmaf(s_w[ci * 48 + co * 16 + kh * 4 + kw], iv, acc[co]);
                }
            }
        }
    }
#pragma unroll
    for (int co = 0; co < 3; ++co)
        out[(((size_t)n * 3 + co) * Hout + oh) * Wout + ow] = __fadd_rn(acc[co], bias[co]);
}

// ---------------- VQ (reference fp32 numerics, unchanged from passing R7) ----------------
__global__ void cnorm_kernel(const float* __restrict__ cb, float* __restrict__ cn)
{
    int k = blockIdx.x * blockDim.x + threadIdx.x;
    if (k < 512) {
        const float* p = cb + (size_t)k * 256;
        float acc = 0.f;
#pragma unroll 4
        for (int d = 0; d < 256; ++d)
            acc = __fadd_rn(acc, __fmul_rn(p[d], p[d]));
        cn[k] = acc;
    }
}

__global__ void __launch_bounds__(256)
vq_argmin_kernel(const float* __restrict__ z, const float* __restrict__ cb,
                 const float* __restrict__ cn, int* __restrict__ q)
{
    __shared__ float s_z[32 * 257];
    __shared__ float s_Z[32];
    __shared__ float s_bd[256];
    __shared__ int   s_bi[256];
    int nh = blockIdx.x;
    int n = nh >> 5, h = nh & 31;
    int tx = threadIdx.x;
    size_t zb = (size_t)n * 262144 + (size_t)h * 32;
#pragma unroll 1
    for (int idx = tx; idx < 256 * 32; idx += 256) {
        int d = idx >> 5, w = idx & 31;
        s_z[w * 257 + d] = 2.0f * z[zb + (size_t)d * 1024 + w];
    }
    __syncthreads();
    if (tx < 32) {
        const float* zr = s_z + tx * 257;
        float acc = 0.f;
#pragma unroll 4
        for (int d = 0; d < 256; ++d) {
            float zv = 0.5f * zr[d];
            acc = __fadd_rn(acc, __fmul_rn(zv, zv));
        }
        s_Z[tx] = acc;
    }
    __syncthreads();

    int m = tx & 31, g = tx >> 5;
    const float* zr = s_z + m * 257;
    float Zm = s_Z[m];
    float best = 3.4028235e38f;
    int bi = 0;
#pragma unroll 1
    for (int t = 0; t < 64; t += 2) {
        int k0 = g + 8 * t;
        int k1 = k0 + 8;
        const float* c0 = cb + (size_t)k0 * 256;
        const float* c1 = cb + (size_t)k1 * 256;
        float A = 0.f, B = 0.f;
#pragma unroll 4
        for (int d = 0; d < 256; ++d) {
            float zv = zr[d];
            A = fmaf(zv, c0[d], A);
            B = fmaf(zv, c1[d], B);
        }
        float t0 = __fadd_rn(__fsub_rn(Zm, A), cn[k0]);
        float t1 = __fadd_rn(__fsub_rn(Zm, B), cn[k1]);
        if (t0 < best) { best = t0; bi = k0; }
        if (t1 < best) { best = t1; bi = k1; }
    }
    s_bd[g * 32 + m] = best;
    s_bi[g * 32 + m] = bi;
    __syncthreads();
    if (tx < 32) {
        float bb = s_bd[tx];
        int   ii = s_bi[tx];
#pragma unroll
        for (int gg = 1; gg < 8; ++gg) {
            float dd = s_bd[gg * 32 + tx];
            int   jj = s_bi[gg * 32 + tx];
            if (dd < bb || (dd == bb && jj < ii)) { bb = dd; ii = jj; }
        }
        q[nh * 32 + tx] = ii;
    }
}

__global__ void vq_gather_kernel(const int* __restrict__ q, const float* __restrict__ cb,
                                 float* __restrict__ zq)
{
    __shared__ int s_q[32];
    int nh = blockIdx.x;
    int n = nh >> 5, h = nh & 31;
    int tx = threadIdx.x;
    if (tx < 32) s_q[tx] = q[nh * 32 + tx];
    __syncthreads();
    size_t zb = (size_t)n * 262144 + (size_t)h * 32;
#pragma unroll 1
    for (int idx = tx; idx < 256 * 32; idx += 256) {
        int d = idx >> 5, w = idx & 31;
        zq[zb + (size_t)d * 1024 + w] = cb[(size_t)s_q[w] * 256 + d];
    }
}

// ---------------- host ----------------
static void run_resblock(const float* X, float* T, float* Y,
                         const float* bn1g, const float* bn1b,
                         const float* c3w, const float* c3b,
                         const float* bn2g, const float* bn2b,
                         const float* c1w, const float* c1b,
                         float* mn, float* rr)
{
    bn_stats_kernel<<<256, 256>>>(X, mn, rr, 16, 256, 1024);
    conv3x3_v2<<<dim3(16 * 8, 8), 256>>>(X, c3w, c3b, mn, rr, bn1g, bn1b, T);
    bn_stats_kernel<<<256, 256>>>(T, mn, rr, 16, 256, 1024);
    conv1x1_v2<<<dim3(16 * 8, 4), 256>>>(T, c1w, c1b, mn, rr, bn2g, bn2b, X, Y);
}

extern "C" void kernel_launch(void* const* d_in, const int* in_sizes, int n_in,
                              void* d_out, int out_size)
{
    (void)in_sizes; (void)n_in; (void)out_size;
    const float* x        = (const float*)d_in[0];
    const float* ec1_w    = (const float*)d_in[1];
    const float* ec1_b    = (const float*)d_in[2];
    const float* ebn1_g   = (const float*)d_in[3];
    const float* ebn1_b   = (const float*)d_in[4];
    const float* ec2_w    = (const float*)d_in[5];
    const float* ec2_b    = (const float*)d_in[6];
    const float* rb_bn1_g = (const float*)d_in[7];
    const float* rb_bn1_b = (const float*)d_in[8];
    const float* rb_c3_w  = (const float*)d_in[9];
    const float* rb_c3_b  = (const float*)d_in[10];
    const float* rb_bn2_g = (const float*)d_in[11];
    const float* rb_bn2_b = (const float*)d_in[12];
    const float* rb_c1_w  = (const float*)d_in[13];
    const float* rb_c1_b  = (const float*)d_in[14];
    const float* dbn1_g   = (const float*)d_in[15];
    const float* dbn1_b   = (const float*)d_in[16];
    const float* dct1_w   = (const float*)d_in[17];
    const float* dct1_b   = (const float*)d_in[18];
    const float* dbn2_g   = (const float*)d_in[19];
    const float* dbn2_b   = (const float*)d_in[20];
    const float* dct2_w   = (const float*)d_in[21];
    const float* dct2_b   = (const float*)d_in[22];
    const float* codebook = (const float*)d_in[23];

    float *A64, *Ba, *Bb, *Bc, *mn, *rr, *cn;
    int* q;
    cudaGetSymbolAddress((void**)&A64, g_A64);
    cudaGetSymbolAddress((void**)&Ba,  g_B32a);
    cudaGetSymbolAddress((void**)&Bb,  g_B32b);
    cudaGetSymbolAddress((void**)&Bc,  g_B32c);
    cudaGetSymbolAddress((void**)&mn,  g_mean);
    cudaGetSymbolAddress((void**)&rr,  g_r);
    cudaGetSymbolAddress((void**)&cn,  g_cnorm);
    cudaGetSymbolAddress((void**)&q,   g_q);

    float* out   = (float*)d_out;
    float* x_rec = out;
    float* z_e   = out + 786432;
    float* z_q   = z_e + 4194304;

    // encoder
    conv4x4s2_v2<false><<<dim3(16 * 32, 8), 256>>>(
        x, ec1_w, ec1_b, nullptr, nullptr, nullptr, nullptr, A64,
        16, 3, 128, 128, 256, 64, 64);
    bn_stats_kernel<<<256, 256>>>(A64, mn, rr, 16, 256, 4096);
    conv4x4s2_v2<true><<<dim3(16 * 8, 8), 256>>>(
        A64, ec2_w, ec2_b, mn, rr, ebn1_g, ebn1_b, Ba,
        16, 256, 64, 64, 256, 32, 32);

    const size_t W3 = (size_t)256 * 256 * 9;
    const size_t W1 = (size_t)256 * 256;
    run_resblock(Ba, Bb, Bc, rb_bn1_g + 0, rb_bn1_b + 0, rb_c3_w + 0 * W3, rb_c3_b + 0,
                 rb_bn2_g + 0, rb_bn2_b + 0, rb_c1_w + 0 * W1, rb_c1_b + 0, mn, rr);
    run_resblock(Bc, Bb, z_e, rb_bn1_g + 256, rb_bn1_b + 256, rb_c3_w + 1 * W3, rb_c3_b + 256,
                 rb_bn2_g + 256, rb_bn2_b + 256, rb_c1_w + 1 * W1, rb_c1_b + 256, mn, rr);

    // VQ
    cnorm_kernel<<<2, 256>>>(codebook, cn);
    vq_argmin_kernel<<<512, 256>>>(z_e, codebook, cn, q);
    vq_gather_kernel<<<512, 256>>>(q, codebook, z_q);

    // decoder
    run_resblock(z_e, Ba, Bb, rb_bn1_g + 512, rb_bn1_b + 512, rb_c3_w + 2 * W3, rb_c3_b + 512,
                 rb_bn2_g + 512, rb_bn2_b + 512, rb_c1_w + 2 * W1, rb_c1_b + 512, mn, rr);
    run_resblock(Bb, Bc, Ba, rb_bn1_g + 768, rb_bn1_b + 768, rb_c3_w + 3 * W3, rb_c3_b + 768,
                 rb_bn2_g + 768, rb_bn2_b + 768, rb_c1_w + 3 * W1, rb_c1_b + 768, mn, rr);

    bn_stats_kernel<<<256, 256>>>(Ba, mn, rr, 16, 256, 1024);
    convT4x4_v2<<<dim3(16 * 32, 4), 256>>>(
        Ba, dct1_w, dct1_b, mn, rr, dbn1_g, dbn1_b, A64,
        16, 256, 32, 32, 256, 64, 64);
    bn_stats_kernel<<<256, 256>>>(A64, mn, rr, 16, 256, 4096);
    convT_out_kernel<<<16 * 64, 256>>>(
        A64, dct2_w, dct2_b, mn, rr, dbn2_g, dbn2_b, x_rec,
        16, 256, 64, 64, 128, 128);
}